// round 1
// baseline (speedup 1.0000x reference)
#include <cuda_runtime.h>

// Problem constants
#define B_   2
#define S_   2048
#define D_   1024
#define H_   16
#define DH_  64
#define M_   4096      /* B_*S_ rows */
#define N_   1024      /* H_*DH_ == D_ */

// Scratch (static device globals — no runtime allocation)
__device__ float g_q  [M_ * N_];
__device__ float g_k  [M_ * N_];
__device__ float g_v  [M_ * N_];
__device__ float g_z  [M_ * N_];
__device__ float g_wot[D_ * N_];

// ---------------------------------------------------------------------------
// 128x128 tile SGEMM: C[M,1024] = A[M,1024] * W[1024,1024]^T + bias
// Both A and W are row-major with K (=1024) contiguous.
// 256 threads, 8x8 register tile per thread, BK=16.
// ---------------------------------------------------------------------------
__device__ __forceinline__ void sgemm128(const float* __restrict__ A,
                                         const float* __restrict__ W,
                                         const float* __restrict__ bias,
                                         float* __restrict__ C)
{
    __shared__ __align__(16) float As[16][128];
    __shared__ __align__(16) float Bs[16][128];

    const int tid = threadIdx.x;
    const int tx  = tid & 15;      // col group (x8)
    const int ty  = tid >> 4;      // row group (x8)
    const int rowBase = blockIdx.y * 128;
    const int colBase = blockIdx.x * 128;
    const int lr = tid >> 2;       // 0..63
    const int lc = tid & 3;        // 0..3

    float acc[8][8];
#pragma unroll
    for (int i = 0; i < 8; ++i)
#pragma unroll
        for (int j = 0; j < 8; ++j) acc[i][j] = 0.f;

    for (int kt = 0; kt < 1024; kt += 16) {
#pragma unroll
        for (int i = 0; i < 2; ++i) {
            const int r = lr + i * 64;
            const float4 va = *(const float4*)(A + (size_t)(rowBase + r) * 1024 + kt + lc * 4);
            As[lc * 4 + 0][r] = va.x;
            As[lc * 4 + 1][r] = va.y;
            As[lc * 4 + 2][r] = va.z;
            As[lc * 4 + 3][r] = va.w;
            const float4 vb = *(const float4*)(W + (size_t)(colBase + r) * 1024 + kt + lc * 4);
            Bs[lc * 4 + 0][r] = vb.x;
            Bs[lc * 4 + 1][r] = vb.y;
            Bs[lc * 4 + 2][r] = vb.z;
            Bs[lc * 4 + 3][r] = vb.w;
        }
        __syncthreads();
#pragma unroll
        for (int kk = 0; kk < 16; ++kk) {
            float a[8], b[8];
            *(float4*)&a[0] = *(const float4*)&As[kk][ty * 8];
            *(float4*)&a[4] = *(const float4*)&As[kk][ty * 8 + 4];
            *(float4*)&b[0] = *(const float4*)&Bs[kk][tx * 8];
            *(float4*)&b[4] = *(const float4*)&Bs[kk][tx * 8 + 4];
#pragma unroll
            for (int i = 0; i < 8; ++i)
#pragma unroll
                for (int j = 0; j < 8; ++j)
                    acc[i][j] = fmaf(a[i], b[j], acc[i][j]);
        }
        __syncthreads();
    }

#pragma unroll
    for (int i = 0; i < 8; ++i) {
        const int r = rowBase + ty * 8 + i;
#pragma unroll
        for (int j = 0; j < 8; j += 4) {
            const int c = colBase + tx * 8 + j;
            float4 o;
            o.x = acc[i][j + 0] + bias[c + 0];
            o.y = acc[i][j + 1] + bias[c + 1];
            o.z = acc[i][j + 2] + bias[c + 2];
            o.w = acc[i][j + 3] + bias[c + 3];
            *(float4*)(C + (size_t)r * 1024 + c) = o;
        }
    }
}

// QKV projection: blockIdx.z selects Q/K/V
__global__ void __launch_bounds__(256)
qkv_kernel(const float* __restrict__ x,
           const float* __restrict__ Wq, const float* __restrict__ Wk,
           const float* __restrict__ Wv,
           const float* __restrict__ bq, const float* __restrict__ bk,
           const float* __restrict__ bv)
{
    const int z = blockIdx.z;
    const float* W = (z == 0) ? Wq : (z == 1) ? Wk : Wv;
    const float* b = (z == 0) ? bq : (z == 1) ? bk : bv;
    float* O       = (z == 0) ? g_q : (z == 1) ? g_k : g_v;
    sgemm128(x, W, b, O);
}

// Output projection: out = z @ WoT^T + b_O
__global__ void __launch_bounds__(256)
out_kernel(const float* __restrict__ bo, float* __restrict__ out)
{
    sgemm128(g_z, g_wot, bo, out);
}

// W_O [H, D, DH] -> g_wot[d][i*64+h]
__global__ void transpose_wo_kernel(const float* __restrict__ Wo)
{
    const int idx = blockIdx.x * 256 + threadIdx.x;   // 0 .. 1048575
    const int h = idx & 63;
    const int i = (idx >> 6) & 15;
    const int d = idx >> 10;
    g_wot[idx] = Wo[((size_t)i * 1024 + d) * 64 + h];
}

// ---------------------------------------------------------------------------
// Flash attention (fp32). One block per (q-tile of 128, head, batch).
// 256 threads, per-thread 8x4 register tile. Online softmax.
// ---------------------------------------------------------------------------
#define FLASH_SMEM ((64 * 128 + 64 * 64 + 64 * 64 + 128 * 68) * 4)  /* 100352 B */

__global__ void __launch_bounds__(256)
flash_kernel()
{
    extern __shared__ __align__(16) float sm[];
    float* const Qs = sm;                    // [dh][r]  64 x 128 (pre-scaled)
    float* const Ks = Qs + 64 * 128;         // [dh][j]  64 x 64
    float* const Vs = Ks + 64 * 64;          // [j][dh]  64 x 64
    float* const Ps = Vs + 64 * 64;          // [r][j]   128 x 68 (stride 68)

    const int qt  = blockIdx.x;   // 0..15
    const int h   = blockIdx.y;   // 0..15
    const int bb  = blockIdx.z;   // 0..1
    const int tid = threadIdx.x;
    const int tx  = tid & 15;     // key-col group (x4)
    const int ty  = tid >> 4;     // q-row group (x8)

    const int qbase = qt * 128;
    const size_t base = (size_t)bb * S_ * 1024 + (size_t)h * 64;
    const float* const Qg = g_q + base;
    const float* const Kg = g_k + base;
    const float* const Vg = g_v + base;

    // Load Q tile transposed, pre-scaled by 1/sqrt(DH) = 0.125
    {
        const int r  = tid & 127;
        const int cg = tid >> 7;   // 0..1
#pragma unroll
        for (int i = 0; i < 8; ++i) {
            const int c4 = cg + i * 2;  // 0..15
            const float4 v = *(const float4*)(Qg + (size_t)(qbase + r) * 1024 + c4 * 4);
            Qs[(c4 * 4 + 0) * 128 + r] = v.x * 0.125f;
            Qs[(c4 * 4 + 1) * 128 + r] = v.y * 0.125f;
            Qs[(c4 * 4 + 2) * 128 + r] = v.z * 0.125f;
            Qs[(c4 * 4 + 3) * 128 + r] = v.w * 0.125f;
        }
    }

    float acc[8][4];
    float m[8], l[8];
#pragma unroll
    for (int i = 0; i < 8; ++i) {
        m[i] = -1e30f;
        l[i] = 0.f;
#pragma unroll
        for (int j = 0; j < 4; ++j) acc[i][j] = 0.f;
    }

    const int ktmax = 2 * qt + 1;
    for (int kt = 0; kt <= ktmax; ++kt) {
        const int kbase = kt * 64;
        __syncthreads();   // previous iteration's Ps/Vs reads complete

        // K transposed [dh][j] (lane-major j -> conflict-free STS)
        {
            const int j  = tid & 63;
            const int kg = tid >> 6;   // 0..3
#pragma unroll
            for (int i = 0; i < 4; ++i) {
                const int c4 = kg + i * 4;
                const float4 v = *(const float4*)(Kg + (size_t)(kbase + j) * 1024 + c4 * 4);
                Ks[(c4 * 4 + 0) * 64 + j] = v.x;
                Ks[(c4 * 4 + 1) * 64 + j] = v.y;
                Ks[(c4 * 4 + 2) * 64 + j] = v.z;
                Ks[(c4 * 4 + 3) * 64 + j] = v.w;
            }
        }
        // V natural [j][dh] (coalesced gmem, float4 STS)
#pragma unroll
        for (int i = 0; i < 4; ++i) {
            const int idx = tid + i * 256;
            const int jj  = idx >> 4;
            const int c4  = idx & 15;
            *(float4*)(Vs + jj * 64 + c4 * 4) =
                *(const float4*)(Vg + (size_t)(kbase + jj) * 1024 + c4 * 4);
        }
        __syncthreads();

        // S = Q K^T (scaled already)
        float s[8][4];
#pragma unroll
        for (int i = 0; i < 8; ++i)
#pragma unroll
            for (int j = 0; j < 4; ++j) s[i][j] = 0.f;

#pragma unroll 16
        for (int kk = 0; kk < 64; ++kk) {
            float a[8], bv[4];
            *(float4*)&a[0]  = *(const float4*)(Qs + kk * 128 + ty * 8);
            *(float4*)&a[4]  = *(const float4*)(Qs + kk * 128 + ty * 8 + 4);
            *(float4*)&bv[0] = *(const float4*)(Ks + kk * 64 + tx * 4);
#pragma unroll
            for (int i = 0; i < 8; ++i)
#pragma unroll
                for (int j = 0; j < 4; ++j)
                    s[i][j] = fmaf(a[i], bv[j], s[i][j]);
        }

        // Causal mask — only the two diagonal-overlapping key tiles need it
        if (kt >= 2 * qt) {
            const int diff = kbase - qbase;   // 0 or 64
#pragma unroll
            for (int i = 0; i < 8; ++i) {
                const int qr = ty * 8 + i;
#pragma unroll
                for (int j = 0; j < 4; ++j)
                    if (diff + tx * 4 + j > qr) s[i][j] = -1e30f;
            }
        }

        // Online softmax (row stats replicated across the 16 tx lanes via shfl)
#pragma unroll
        for (int i = 0; i < 8; ++i) {
            float mx = fmaxf(fmaxf(s[i][0], s[i][1]), fmaxf(s[i][2], s[i][3]));
#pragma unroll
            for (int off = 8; off > 0; off >>= 1)
                mx = fmaxf(mx, __shfl_xor_sync(0xffffffffu, mx, off));
            const float mn    = fmaxf(m[i], mx);
            const float alpha = __expf(m[i] - mn);
            float rs = 0.f;
#pragma unroll
            for (int j = 0; j < 4; ++j) {
                const float p = __expf(s[i][j] - mn);
                s[i][j] = p;
                rs += p;
            }
#pragma unroll
            for (int off = 8; off > 0; off >>= 1)
                rs += __shfl_xor_sync(0xffffffffu, rs, off);
            l[i] = l[i] * alpha + rs;
            m[i] = mn;
#pragma unroll
            for (int j = 0; j < 4; ++j) acc[i][j] *= alpha;
        }

        // Stage P [r][j] (stride 68 -> 2-way STS.128 worst case)
#pragma unroll
        for (int i = 0; i < 8; ++i)
            *(float4*)(Ps + (ty * 8 + i) * 68 + tx * 4) = *(float4*)&s[i][0];
        __syncthreads();

        // O += P V
#pragma unroll 4
        for (int j4 = 0; j4 < 16; ++j4) {
            float a[8][4];
            float bw[4][4];
#pragma unroll
            for (int i = 0; i < 8; ++i)
                *(float4*)&a[i][0] = *(const float4*)(Ps + (ty * 8 + i) * 68 + j4 * 4);
#pragma unroll
            for (int u = 0; u < 4; ++u)
                *(float4*)&bw[u][0] = *(const float4*)(Vs + (j4 * 4 + u) * 64 + tx * 4);
#pragma unroll
            for (int i = 0; i < 8; ++i)
#pragma unroll
                for (int u = 0; u < 4; ++u)
#pragma unroll
                    for (int j = 0; j < 4; ++j)
                        acc[i][j] = fmaf(a[i][u], bw[u][j], acc[i][j]);
        }
    }

    // Normalize and write z
    float* const Zg = g_z + base;
#pragma unroll
    for (int i = 0; i < 8; ++i) {
        const float inv = 1.f / l[i];
        float4 o;
        o.x = acc[i][0] * inv;
        o.y = acc[i][1] * inv;
        o.z = acc[i][2] * inv;
        o.w = acc[i][3] * inv;
        *(float4*)(Zg + (size_t)(qbase + ty * 8 + i) * 1024 + tx * 4) = o;
    }
}

// ---------------------------------------------------------------------------
extern "C" void kernel_launch(void* const* d_in, const int* in_sizes, int n_in,
                              void* d_out, int out_size)
{
    (void)in_sizes; (void)n_in; (void)out_size;
    const float* x  = (const float*)d_in[0];
    const float* Wq = (const float*)d_in[1];
    const float* Wk = (const float*)d_in[2];
    const float* Wv = (const float*)d_in[3];
    const float* Wo = (const float*)d_in[4];
    const float* bq = (const float*)d_in[5];
    const float* bk = (const float*)d_in[6];
    const float* bv = (const float*)d_in[7];
    const float* bo = (const float*)d_in[8];
    float* out = (float*)d_out;

    cudaFuncSetAttribute(flash_kernel,
                         cudaFuncAttributeMaxDynamicSharedMemorySize, FLASH_SMEM);

    qkv_kernel<<<dim3(8, 32, 3), 256>>>(x, Wq, Wk, Wv, bq, bk, bv);
    transpose_wo_kernel<<<4096, 256>>>(Wo);
    flash_kernel<<<dim3(16, 16, 2), 256, FLASH_SMEM>>>();
    out_kernel<<<dim3(8, 32, 1), 256>>>(bo, out);
}

// round 2
// speedup vs baseline: 1.8767x; 1.8767x over previous
#include <cuda_runtime.h>
#include <cstdint>

// Problem constants
#define B_   2
#define S_   2048
#define D_   1024
#define H_   16
#define DH_  64
#define M_   4096      /* B_*S_ rows */
#define N_   1024      /* H_*DH_ == D_ */

// Scratch (static device globals — no runtime allocation)
__device__ float g_q  [M_ * N_];
__device__ float g_k  [M_ * N_];
__device__ float g_v  [M_ * N_];
__device__ float g_z  [M_ * N_];     // tf32-rounded at write
__device__ float g_wot[D_ * N_];     // tf32-rounded
__device__ float g_xc [M_ * D_];     // tf32-rounded copy of x
__device__ float g_wqkv[3 * N_ * D_]; // tf32-rounded W_Q|W_K|W_V

// ---------------------------------------------------------------------------
__device__ __forceinline__ float tf32r(float x)
{
    unsigned u;
    asm("cvt.rna.tf32.f32 %0, %1;" : "=r"(u) : "f"(x));
    return __uint_as_float(u);
}

// Round-to-tf32 elementwise copy (float4 per thread)
__global__ void __launch_bounds__(256)
cvt4_kernel(const float* __restrict__ src, float* __restrict__ dst)
{
    const int idx = blockIdx.x * 256 + threadIdx.x;
    float4 v = ((const float4*)src)[idx];
    v.x = tf32r(v.x); v.y = tf32r(v.y); v.z = tf32r(v.z); v.w = tf32r(v.w);
    ((float4*)dst)[idx] = v;
}

// W_O [H, D, DH] -> g_wot[d][i*64+h], tf32-rounded
__global__ void __launch_bounds__(256)
transpose_wo_kernel(const float* __restrict__ Wo)
{
    const int idx = blockIdx.x * 256 + threadIdx.x;   // 0 .. 1048575
    const int h = idx & 63;
    const int i = (idx >> 6) & 15;
    const int d = idx >> 10;
    g_wot[idx] = tf32r(Wo[((size_t)i * 1024 + d) * 64 + h]);
}

// ---------------------------------------------------------------------------
// TF32 tensor-core GEMM: C[4096,1024] = A[4096,1024] * W[1024,1024]^T + bias
// A, W row-major, K contiguous, values already tf32-rounded.
// Block 128x128, BK=32, 8 warps (2x4), warp tile 64x32, mma m16n8k8.
// cp.async double-buffered smem with SW128 swizzle; ldmatrix fragment loads.
// ---------------------------------------------------------------------------
#define TG_SMEM 65536
#define SWZ(row, chunk) (((row) << 7) + (((chunk) ^ ((row) & 7)) << 4))

__device__ __forceinline__ void stage_load(const float* __restrict__ A,
                                           const float* __restrict__ W,
                                           int rowBase, int colBase, int kt,
                                           uint32_t sdst, int tid)
{
#pragma unroll
    for (int i = 0; i < 4; ++i) {
        const int cid = tid + i * 256;
        const int row = cid >> 3;
        const int kc  = cid & 7;
        const float* gA = A + (size_t)(rowBase + row) * 1024 + kt * 32 + kc * 4;
        const float* gB = W + (size_t)(colBase + row) * 1024 + kt * 32 + kc * 4;
        const uint32_t dA = sdst + SWZ(row, kc);
        const uint32_t dB = sdst + 16384 + SWZ(row, kc);
        asm volatile("cp.async.cg.shared.global [%0], [%1], 16;\n" :: "r"(dA), "l"(gA));
        asm volatile("cp.async.cg.shared.global [%0], [%1], 16;\n" :: "r"(dB), "l"(gB));
    }
}

__device__ __forceinline__ void tgemm128(const float* __restrict__ A,
                                         const float* __restrict__ W,
                                         const float* __restrict__ bias,
                                         float* __restrict__ C,
                                         float* sm)
{
    const uint32_t sbase = (uint32_t)__cvta_generic_to_shared(sm);
    const int tid  = threadIdx.x;
    const int lane = tid & 31;
    const int w    = tid >> 5;
    const int wr   = w & 1;       // 0..1 (64-row group)
    const int wc   = w >> 1;      // 0..3 (32-col group)
    const int rowBase = blockIdx.y * 128;
    const int colBase = blockIdx.x * 128;

    float acc[4][4][4] = {};

    // ldmatrix lane row bases
    const int rA = wr * 64 + (lane & 15);       // + ti*16
    const int rB = wc * 32 + (lane & 7);        // + ci*8
    const int cAsel = lane >> 4;                // 0/1
    const int cBsel = (lane >> 3) & 1;          // 0/1

    stage_load(A, W, rowBase, colBase, 0, sbase, tid);
    asm volatile("cp.async.commit_group;\n");

    for (int kt = 0; kt < 32; ++kt) {
        __syncthreads();   // all warps done with buffer (kt+1)&1 from iter kt-1
        if (kt + 1 < 32)
            stage_load(A, W, rowBase, colBase, kt + 1, sbase + ((kt + 1) & 1) * 32768, tid);
        asm volatile("cp.async.commit_group;\n");
        asm volatile("cp.async.wait_group 1;\n");
        __syncthreads();

        const uint32_t aBase = sbase + (kt & 1) * 32768;
        const uint32_t bBase = aBase + 16384;
#pragma unroll
        for (int km = 0; km < 4; ++km) {
            uint32_t a[4][4], b[4][2];
#pragma unroll
            for (int ti = 0; ti < 4; ++ti) {
                const int row = rA + ti * 16;
                const uint32_t addr = aBase + (row << 7) + ((((km << 1) + cAsel) ^ (row & 7)) << 4);
                asm volatile("ldmatrix.sync.aligned.m8n8.x4.shared.b16 {%0,%1,%2,%3}, [%4];"
                             : "=r"(a[ti][0]), "=r"(a[ti][1]), "=r"(a[ti][2]), "=r"(a[ti][3])
                             : "r"(addr));
            }
#pragma unroll
            for (int ci = 0; ci < 4; ++ci) {
                const int row = rB + ci * 8;
                const uint32_t addr = bBase + (row << 7) + ((((km << 1) + cBsel) ^ (row & 7)) << 4);
                asm volatile("ldmatrix.sync.aligned.m8n8.x2.shared.b16 {%0,%1}, [%2];"
                             : "=r"(b[ci][0]), "=r"(b[ci][1])
                             : "r"(addr));
            }
#pragma unroll
            for (int ti = 0; ti < 4; ++ti)
#pragma unroll
                for (int ci = 0; ci < 4; ++ci) {
                    float* c = acc[ti][ci];
                    asm volatile(
                        "mma.sync.aligned.m16n8k8.row.col.f32.tf32.tf32.f32 "
                        "{%0,%1,%2,%3}, {%4,%5,%6,%7}, {%8,%9}, {%0,%1,%2,%3};"
                        : "+f"(c[0]), "+f"(c[1]), "+f"(c[2]), "+f"(c[3])
                        : "r"(a[ti][0]), "r"(a[ti][1]), "r"(a[ti][2]), "r"(a[ti][3]),
                          "r"(b[ci][0]), "r"(b[ci][1]));
                }
        }
    }

    // Epilogue: c0,c1 -> row g, cols 2tg,2tg+1 ; c2,c3 -> row g+8
#pragma unroll
    for (int ti = 0; ti < 4; ++ti) {
        const int r0 = rowBase + wr * 64 + ti * 16 + (lane >> 2);
#pragma unroll
        for (int half = 0; half < 2; ++half) {
            const int r = r0 + half * 8;
#pragma unroll
            for (int ci = 0; ci < 4; ++ci) {
                const int c = colBase + wc * 32 + ci * 8 + 2 * (lane & 3);
                float2 o;
                o.x = acc[ti][ci][half * 2 + 0] + bias[c];
                o.y = acc[ti][ci][half * 2 + 1] + bias[c + 1];
                *(float2*)(C + (size_t)r * 1024 + c) = o;
            }
        }
    }
}

// QKV projection: blockIdx.z selects Q/K/V
__global__ void __launch_bounds__(256, 2)
qkv_kernel(const float* __restrict__ bq, const float* __restrict__ bk,
           const float* __restrict__ bv)
{
    extern __shared__ float sm[];
    const int z = blockIdx.z;
    const float* W = g_wqkv + (size_t)z * 1048576;
    const float* b = (z == 0) ? bq : (z == 1) ? bk : bv;
    float* O       = (z == 0) ? g_q : (z == 1) ? g_k : g_v;
    tgemm128(g_xc, W, b, O, sm);
}

// Output projection: out = z @ WoT^T + b_O
__global__ void __launch_bounds__(256, 2)
out_kernel(const float* __restrict__ bo, float* __restrict__ out)
{
    extern __shared__ float sm[];
    tgemm128(g_z, g_wot, bo, out, sm);
}

// ---------------------------------------------------------------------------
// Flash attention (fp32). One block per (q-tile of 128, head, batch).
// 256 threads, per-thread 8x4 register tile. Online softmax.
// ---------------------------------------------------------------------------
#define FLASH_SMEM ((64 * 128 + 64 * 64 + 64 * 64 + 128 * 68) * 4)  /* 100352 B */

__global__ void __launch_bounds__(256)
flash_kernel()
{
    extern __shared__ __align__(16) float sm[];
    float* const Qs = sm;                    // [dh][r]  64 x 128 (pre-scaled)
    float* const Ks = Qs + 64 * 128;         // [dh][j]  64 x 64
    float* const Vs = Ks + 64 * 64;          // [j][dh]  64 x 64
    float* const Ps = Vs + 64 * 64;          // [r][j]   128 x 68 (stride 68)

    const int qt  = blockIdx.x;   // 0..15
    const int h   = blockIdx.y;   // 0..15
    const int bb  = blockIdx.z;   // 0..1
    const int tid = threadIdx.x;
    const int tx  = tid & 15;     // key-col group (x4)
    const int ty  = tid >> 4;     // q-row group (x8)

    const int qbase = qt * 128;
    const size_t base = (size_t)bb * S_ * 1024 + (size_t)h * 64;
    const float* const Qg = g_q + base;
    const float* const Kg = g_k + base;
    const float* const Vg = g_v + base;

    // Load Q tile transposed, pre-scaled by 1/sqrt(DH) = 0.125
    {
        const int r  = tid & 127;
        const int cg = tid >> 7;   // 0..1
#pragma unroll
        for (int i = 0; i < 8; ++i) {
            const int c4 = cg + i * 2;  // 0..15
            const float4 v = *(const float4*)(Qg + (size_t)(qbase + r) * 1024 + c4 * 4);
            Qs[(c4 * 4 + 0) * 128 + r] = v.x * 0.125f;
            Qs[(c4 * 4 + 1) * 128 + r] = v.y * 0.125f;
            Qs[(c4 * 4 + 2) * 128 + r] = v.z * 0.125f;
            Qs[(c4 * 4 + 3) * 128 + r] = v.w * 0.125f;
        }
    }

    float acc[8][4];
    float m[8], l[8];
#pragma unroll
    for (int i = 0; i < 8; ++i) {
        m[i] = -1e30f;
        l[i] = 0.f;
#pragma unroll
        for (int j = 0; j < 4; ++j) acc[i][j] = 0.f;
    }

    const int ktmax = 2 * qt + 1;
    for (int kt = 0; kt <= ktmax; ++kt) {
        const int kbase = kt * 64;
        __syncthreads();   // previous iteration's Ps/Vs reads complete

        // K transposed [dh][j] (lane-major j -> conflict-free STS)
        {
            const int j  = tid & 63;
            const int kg = tid >> 6;   // 0..3
#pragma unroll
            for (int i = 0; i < 4; ++i) {
                const int c4 = kg + i * 4;
                const float4 v = *(const float4*)(Kg + (size_t)(kbase + j) * 1024 + c4 * 4);
                Ks[(c4 * 4 + 0) * 64 + j] = v.x;
                Ks[(c4 * 4 + 1) * 64 + j] = v.y;
                Ks[(c4 * 4 + 2) * 64 + j] = v.z;
                Ks[(c4 * 4 + 3) * 64 + j] = v.w;
            }
        }
        // V natural [j][dh] (coalesced gmem, float4 STS)
#pragma unroll
        for (int i = 0; i < 4; ++i) {
            const int idx = tid + i * 256;
            const int jj  = idx >> 4;
            const int c4  = idx & 15;
            *(float4*)(Vs + jj * 64 + c4 * 4) =
                *(const float4*)(Vg + (size_t)(kbase + jj) * 1024 + c4 * 4);
        }
        __syncthreads();

        // S = Q K^T (scaled already)
        float s[8][4];
#pragma unroll
        for (int i = 0; i < 8; ++i)
#pragma unroll
            for (int j = 0; j < 4; ++j) s[i][j] = 0.f;

#pragma unroll 16
        for (int kk = 0; kk < 64; ++kk) {
            float a[8], bv[4];
            *(float4*)&a[0]  = *(const float4*)(Qs + kk * 128 + ty * 8);
            *(float4*)&a[4]  = *(const float4*)(Qs + kk * 128 + ty * 8 + 4);
            *(float4*)&bv[0] = *(const float4*)(Ks + kk * 64 + tx * 4);
#pragma unroll
            for (int i = 0; i < 8; ++i)
#pragma unroll
                for (int j = 0; j < 4; ++j)
                    s[i][j] = fmaf(a[i], bv[j], s[i][j]);
        }

        // Causal mask — only the two diagonal-overlapping key tiles need it
        if (kt >= 2 * qt) {
            const int diff = kbase - qbase;   // 0 or 64
#pragma unroll
            for (int i = 0; i < 8; ++i) {
                const int qr = ty * 8 + i;
#pragma unroll
                for (int j = 0; j < 4; ++j)
                    if (diff + tx * 4 + j > qr) s[i][j] = -1e30f;
            }
        }

        // Online softmax (row stats replicated across the 16 tx lanes via shfl)
#pragma unroll
        for (int i = 0; i < 8; ++i) {
            float mx = fmaxf(fmaxf(s[i][0], s[i][1]), fmaxf(s[i][2], s[i][3]));
#pragma unroll
            for (int off = 8; off > 0; off >>= 1)
                mx = fmaxf(mx, __shfl_xor_sync(0xffffffffu, mx, off));
            const float mn    = fmaxf(m[i], mx);
            const float alpha = __expf(m[i] - mn);
            float rs = 0.f;
#pragma unroll
            for (int j = 0; j < 4; ++j) {
                const float p = __expf(s[i][j] - mn);
                s[i][j] = p;
                rs += p;
            }
#pragma unroll
            for (int off = 8; off > 0; off >>= 1)
                rs += __shfl_xor_sync(0xffffffffu, rs, off);
            l[i] = l[i] * alpha + rs;
            m[i] = mn;
#pragma unroll
            for (int j = 0; j < 4; ++j) acc[i][j] *= alpha;
        }

        // Stage P [r][j] (stride 68 -> 2-way STS.128 worst case)
#pragma unroll
        for (int i = 0; i < 8; ++i)
            *(float4*)(Ps + (ty * 8 + i) * 68 + tx * 4) = *(float4*)&s[i][0];
        __syncthreads();

        // O += P V
#pragma unroll 4
        for (int j4 = 0; j4 < 16; ++j4) {
            float a[8][4];
            float bw[4][4];
#pragma unroll
            for (int i = 0; i < 8; ++i)
                *(float4*)&a[i][0] = *(const float4*)(Ps + (ty * 8 + i) * 68 + j4 * 4);
#pragma unroll
            for (int u = 0; u < 4; ++u)
                *(float4*)&bw[u][0] = *(const float4*)(Vs + (j4 * 4 + u) * 64 + tx * 4);
#pragma unroll
            for (int i = 0; i < 8; ++i)
#pragma unroll
                for (int u = 0; u < 4; ++u)
#pragma unroll
                    for (int j = 0; j < 4; ++j)
                        acc[i][j] = fmaf(a[i][u], bw[u][j], acc[i][j]);
        }
    }

    // Normalize and write z (tf32-rounded: z feeds the tf32 out-projection GEMM)
    float* const Zg = g_z + base;
#pragma unroll
    for (int i = 0; i < 8; ++i) {
        const float inv = 1.f / l[i];
        float4 o;
        o.x = tf32r(acc[i][0] * inv);
        o.y = tf32r(acc[i][1] * inv);
        o.z = tf32r(acc[i][2] * inv);
        o.w = tf32r(acc[i][3] * inv);
        *(float4*)(Zg + (size_t)(qbase + ty * 8 + i) * 1024 + tx * 4) = o;
    }
}

// ---------------------------------------------------------------------------
extern "C" void kernel_launch(void* const* d_in, const int* in_sizes, int n_in,
                              void* d_out, int out_size)
{
    (void)in_sizes; (void)n_in; (void)out_size;
    const float* x  = (const float*)d_in[0];
    const float* Wq = (const float*)d_in[1];
    const float* Wk = (const float*)d_in[2];
    const float* Wv = (const float*)d_in[3];
    const float* Wo = (const float*)d_in[4];
    const float* bq = (const float*)d_in[5];
    const float* bk = (const float*)d_in[6];
    const float* bv = (const float*)d_in[7];
    const float* bo = (const float*)d_in[8];
    float* out = (float*)d_out;

    cudaFuncSetAttribute(flash_kernel,
                         cudaFuncAttributeMaxDynamicSharedMemorySize, FLASH_SMEM);
    cudaFuncSetAttribute(qkv_kernel,
                         cudaFuncAttributeMaxDynamicSharedMemorySize, TG_SMEM);
    cudaFuncSetAttribute(out_kernel,
                         cudaFuncAttributeMaxDynamicSharedMemorySize, TG_SMEM);

    // device-global base pointers for the cvt pre-pass
    float *p_xc, *p_wqkv;
    cudaGetSymbolAddress((void**)&p_xc,   g_xc);
    cudaGetSymbolAddress((void**)&p_wqkv, g_wqkv);

    // tf32-round inputs of the tensor GEMMs
    cvt4_kernel<<<4096, 256>>>(x,  p_xc);                    // 4096x1024
    cvt4_kernel<<<1024, 256>>>(Wq, p_wqkv + 0 * 1048576);    // 1024x1024 each
    cvt4_kernel<<<1024, 256>>>(Wk, p_wqkv + 1 * 1048576);
    cvt4_kernel<<<1024, 256>>>(Wv, p_wqkv + 2 * 1048576);
    transpose_wo_kernel<<<4096, 256>>>(Wo);

    qkv_kernel<<<dim3(8, 32, 3), 256, TG_SMEM>>>(bq, bk, bv);
    flash_kernel<<<dim3(16, 16, 2), 256, FLASH_SMEM>>>();
    out_kernel<<<dim3(8, 32, 1), 256, TG_SMEM>>>(bo, out);
}

// round 3
// speedup vs baseline: 6.9827x; 3.7208x over previous
#include <cuda_runtime.h>
#include <cuda_fp16.h>
#include <cstdint>

// Problem constants
#define B_   2
#define S_   2048
#define D_   1024
#define H_   16
#define DH_  64
#define M_   4096      /* B_*S_ rows */

// Q scale: 1/sqrt(64) * log2(e)  (log2e folded so softmax uses pure 2^x)
#define QSCALE 0.1803368801111204f

// Scratch (static device globals — no runtime allocation)
__device__ __half g_xh  [M_ * D_];
__device__ __half g_wh  [3 * D_ * D_];
__device__ __half g_woth[D_ * D_];
__device__ __half g_qh  [M_ * D_];
__device__ __half g_kh  [M_ * D_];
__device__ __half g_vh  [M_ * D_];
__device__ __half g_zh  [M_ * D_];

// ---------------------------------------------------------------------------
// small helpers
// ---------------------------------------------------------------------------
__device__ __forceinline__ float ex2f(float x)
{
    float y;
    asm("ex2.approx.f32 %0, %1;" : "=f"(y) : "f"(x));
    return y;
}
__device__ __forceinline__ uint32_t packh2(float lo, float hi)
{
    uint32_t d;
    asm("cvt.rn.f16x2.f32 %0, %1, %2;" : "=r"(d) : "f"(hi), "f"(lo));
    return d;
}
__device__ __forceinline__ uint32_t h2ex2(uint32_t x)
{
    uint32_t d;
    asm("ex2.approx.f16x2 %0, %1;" : "=r"(d) : "r"(x));
    return d;
}
__device__ __forceinline__ void mma16816(float c[4], const uint32_t a[4],
                                         uint32_t b0, uint32_t b1)
{
    asm volatile(
        "mma.sync.aligned.m16n8k16.row.col.f32.f16.f16.f32 "
        "{%0,%1,%2,%3},{%4,%5,%6,%7},{%8,%9},{%0,%1,%2,%3};"
        : "+f"(c[0]), "+f"(c[1]), "+f"(c[2]), "+f"(c[3])
        : "r"(a[0]), "r"(a[1]), "r"(a[2]), "r"(a[3]), "r"(b0), "r"(b1));
}
__device__ __forceinline__ void ldsm4(uint32_t r[4], uint32_t addr)
{
    asm volatile("ldmatrix.sync.aligned.m8n8.x4.shared.b16 {%0,%1,%2,%3}, [%4];"
                 : "=r"(r[0]), "=r"(r[1]), "=r"(r[2]), "=r"(r[3]) : "r"(addr));
}
__device__ __forceinline__ void ldsm4t(uint32_t r[4], uint32_t addr)
{
    asm volatile("ldmatrix.sync.aligned.m8n8.x4.trans.shared.b16 {%0,%1,%2,%3}, [%4];"
                 : "=r"(r[0]), "=r"(r[1]), "=r"(r[2]), "=r"(r[3]) : "r"(addr));
}

// ---------------------------------------------------------------------------
// pack kernels: fp32 -> fp16
// ---------------------------------------------------------------------------
__global__ void __launch_bounds__(256)
pack_half_kernel(const float* __restrict__ src, __half* __restrict__ dst)
{
    const int i = blockIdx.x * 256 + threadIdx.x;
    const float4 v = ((const float4*)src)[i];
    __half2 h0 = __floats2half2_rn(v.x, v.y);
    __half2 h1 = __floats2half2_rn(v.z, v.w);
    ((__half2*)dst)[2 * i]     = h0;
    ((__half2*)dst)[2 * i + 1] = h1;
}

// W_O [H, D, DH] -> g_woth[d][i*64+h] (half)
__global__ void __launch_bounds__(256)
transpose_wo_kernel(const float* __restrict__ Wo)
{
    const int idx = blockIdx.x * 256 + threadIdx.x;   // 0 .. 1048575
    const int h = idx & 63;
    const int i = (idx >> 6) & 15;
    const int d = idx >> 10;
    g_woth[idx] = __float2half(Wo[((size_t)i * 1024 + d) * 64 + h]);
}

// ---------------------------------------------------------------------------
// FP16 tensor GEMM: C[4096,1024] = A[4096,1024] * W[1024,1024]^T + bias
// A, W half row-major (K contiguous). Block 128x128, BK=64, 8 warps (2x4),
// warp tile 64x32, mma m16n8k16, cp.async double buffer, SW128 swizzle.
// Output: half (optionally scaled) or float.
// ---------------------------------------------------------------------------
#define TG_SMEM 65536

__device__ __forceinline__ void hstage(const __half* __restrict__ A,
                                       const __half* __restrict__ W,
                                       int rowBase, int colBase, int kt,
                                       uint32_t sdst, int tid)
{
#pragma unroll
    for (int i = 0; i < 8; ++i) {
        const int cid = tid + i * 256;          // 0..2047
        const int row = (cid >> 3) & 127;
        const int kc  = cid & 7;
        const __half* src = (cid < 1024)
            ? A + (size_t)(rowBase + row) * 1024 + kt * 64 + kc * 8
            : W + (size_t)(colBase + row) * 1024 + kt * 64 + kc * 8;
        const uint32_t dst = sdst + ((cid < 1024) ? 0 : 16384)
                           + (row << 7) + (((kc ^ (row & 7))) << 4);
        asm volatile("cp.async.cg.shared.global [%0], [%1], 16;\n" :: "r"(dst), "l"(src));
    }
}

template <int OUT_HALF>
__device__ __forceinline__ void hgemm128(const __half* __restrict__ A,
                                         const __half* __restrict__ W,
                                         const float* __restrict__ bias,
                                         void* __restrict__ Cout,
                                         float oscale, float* sm)
{
    const uint32_t sbase = (uint32_t)__cvta_generic_to_shared(sm);
    const int tid  = threadIdx.x;
    const int lane = tid & 31;
    const int w    = tid >> 5;
    const int wr   = w & 1;       // 64-row group
    const int wc   = w >> 1;      // 32-col group
    const int rowBase = blockIdx.y * 128;
    const int colBase = blockIdx.x * 128;

    float acc[4][4][4] = {};

    const int lane7  = lane & 7;
    const int rA     = wr * 64 + (lane & 15);
    const int cA     = lane >> 4;
    const int rBsel  = wc * 32 + ((lane >> 4) << 3) + lane7;  // + p*16
    const int bPar   = (lane >> 3) & 1;

    hstage(A, W, rowBase, colBase, 0, sbase, tid);
    asm volatile("cp.async.commit_group;\n");

    for (int kt = 0; kt < 16; ++kt) {
        __syncthreads();
        if (kt + 1 < 16)
            hstage(A, W, rowBase, colBase, kt + 1, sbase + ((kt + 1) & 1) * 32768, tid);
        asm volatile("cp.async.commit_group;\n");
        asm volatile("cp.async.wait_group 1;\n");
        __syncthreads();

        const uint32_t aBase = sbase + (kt & 1) * 32768;
        const uint32_t bBase = aBase + 16384;
#pragma unroll
        for (int kk = 0; kk < 4; ++kk) {
            uint32_t a[4][4], b[4][2];
#pragma unroll
            for (int mt = 0; mt < 4; ++mt) {
                const int row = rA + mt * 16;
                const uint32_t addr = aBase + (row << 7)
                    + ((((kk << 1) + cA) ^ (row & 7)) << 4);
                ldsm4(a[mt], addr);
            }
#pragma unroll
            for (int p = 0; p < 2; ++p) {
                const int row = rBsel + p * 16;
                const uint32_t addr = bBase + (row << 7)
                    + ((((kk << 1) + bPar) ^ lane7) << 4);
                uint32_t t[4];
                ldsm4(t, addr);
                b[2 * p][0] = t[0]; b[2 * p][1] = t[1];
                b[2 * p + 1][0] = t[2]; b[2 * p + 1][1] = t[3];
            }
#pragma unroll
            for (int mt = 0; mt < 4; ++mt)
#pragma unroll
                for (int nt = 0; nt < 4; ++nt)
                    mma16816(acc[mt][nt], a[mt], b[nt][0], b[nt][1]);
        }
    }

    // Epilogue
#pragma unroll
    for (int mt = 0; mt < 4; ++mt) {
        const int r0 = rowBase + wr * 64 + mt * 16 + (lane >> 2);
#pragma unroll
        for (int half_ = 0; half_ < 2; ++half_) {
            const int r = r0 + half_ * 8;
#pragma unroll
            for (int nt = 0; nt < 4; ++nt) {
                const int c = colBase + wc * 32 + nt * 8 + 2 * (lane & 3);
                const float v0 = (acc[mt][nt][half_ * 2 + 0] + bias[c])     * oscale;
                const float v1 = (acc[mt][nt][half_ * 2 + 1] + bias[c + 1]) * oscale;
                if (OUT_HALF) {
                    __half2* p = (__half2*)((__half*)Cout + (size_t)r * 1024 + c);
                    *p = __floats2half2_rn(v0, v1);
                } else {
                    float2* p = (float2*)((float*)Cout + (size_t)r * 1024 + c);
                    *p = make_float2(v0, v1);
                }
            }
        }
    }
}

// QKV projection: blockIdx.z selects Q/K/V (q scaled by QSCALE)
__global__ void __launch_bounds__(256, 2)
qkv_kernel(const float* __restrict__ bq, const float* __restrict__ bk,
           const float* __restrict__ bv)
{
    extern __shared__ float sm[];
    const int z = blockIdx.z;
    const __half* W = g_wh + (size_t)z * 1048576;
    const float* b  = (z == 0) ? bq : (z == 1) ? bk : bv;
    __half* O       = (z == 0) ? g_qh : (z == 1) ? g_kh : g_vh;
    const float sc  = (z == 0) ? QSCALE : 1.f;
    hgemm128<1>(g_xh, W, b, O, sc, sm);
}

// Output projection: out = z @ WoT^T + b_O (float out)
__global__ void __launch_bounds__(256, 2)
out_kernel(const float* __restrict__ bo, float* __restrict__ out)
{
    extern __shared__ float sm[];
    hgemm128<0>(g_zh, g_woth, bo, out, 1.f, sm);
}

// ---------------------------------------------------------------------------
// FP16 tensor-core flash attention.
// CTA: 128 q-rows, 8 warps x 16 rows, key tiles of 64, DH=64.
// Q fragments register-resident; K/V double-buffered cp.async smem.
// Softmax exps via ex2.approx.f16x2; row-sum via ones-column mma.
// ---------------------------------------------------------------------------
#define FL_SMEM (16384 + 16384 + 16384)   /* Qs + K(2) + V(2) = 48KB */

__global__ void __launch_bounds__(256)
flash_kernel()
{
    extern __shared__ __align__(16) char smc[];
    const uint32_t sQ = (uint32_t)__cvta_generic_to_shared(smc);
    const uint32_t sK = sQ + 16384;
    const uint32_t sV = sK + 16384;

    const int qt  = 15 - blockIdx.x;  // heavy CTAs first
    const int h   = blockIdx.y;
    const int bb  = blockIdx.z;
    const int tid = threadIdx.x;
    const int lane = tid & 31;
    const int wid  = tid >> 5;
    const int lane7 = lane & 7;

    const int qbase = qt * 128;
    const int wrow  = wid * 16;
    const size_t base = (size_t)bb * S_ * 1024 + (size_t)h * 64;
    const __half* const Qg = g_qh + base;
    const __half* const Kg = g_kh + base;
    const __half* const Vg = g_vh + base;

    // ---- stage Q (all 128 rows) + K/V tile 0 ----
#pragma unroll
    for (int i = 0; i < 4; ++i) {
        const int cid = tid + i * 256;          // 0..1023
        const int row = cid >> 3;
        const int kc  = cid & 7;
        const __half* src = Qg + (size_t)(qbase + row) * 1024 + kc * 8;
        const uint32_t dst = sQ + (row << 7) + ((kc ^ (row & 7)) << 4);
        asm volatile("cp.async.cg.shared.global [%0], [%1], 16;\n" :: "r"(dst), "l"(src));
    }
#pragma unroll
    for (int i = 0; i < 4; ++i) {
        const int cid = tid + i * 256;          // 0..1023 : 512 K, 512 V
        const int row = (cid >> 3) & 63;
        const int kc  = cid & 7;
        const __half* src = ((cid < 512) ? Kg : Vg) + (size_t)row * 1024 + kc * 8;
        const uint32_t dst = ((cid < 512) ? sK : sV)
                           + (row << 7) + ((kc ^ (row & 7)) << 4);
        asm volatile("cp.async.cg.shared.global [%0], [%1], 16;\n" :: "r"(dst), "l"(src));
    }
    asm volatile("cp.async.commit_group;\n");

    // per-thread ldmatrix selectors
    const int qRow   = wrow + (lane & 15);
    const int qCsel  = lane >> 4;
    const int kRowSel = ((lane >> 4) << 3) + lane7;   // + p*16
    const int kPar    = (lane >> 3) & 1;
    const int vRow    = lane & 15;                    // + kt16*16
    const int vCsel   = lane >> 4;                    // + 2*p

    uint32_t qa[4][4];
    float oacc[8][4] = {};
    float lacc[4] = {};
    float mrow0 = -1e30f, mrow1 = -1e30f;

    const int ntile = 2 * qt + 2;
    for (int kt = 0; kt < ntile; ++kt) {
        __syncthreads();  // buffer-reuse guard
        if (kt + 1 < ntile) {
            const int kb2 = (kt + 1) * 64;
            const uint32_t boff = ((kt + 1) & 1) * 8192;
#pragma unroll
            for (int i = 0; i < 4; ++i) {
                const int cid = tid + i * 256;
                const int row = (cid >> 3) & 63;
                const int kc  = cid & 7;
                const __half* src = ((cid < 512) ? Kg : Vg)
                                  + (size_t)(kb2 + row) * 1024 + kc * 8;
                const uint32_t dst = ((cid < 512) ? sK : sV) + boff
                                   + (row << 7) + ((kc ^ (row & 7)) << 4);
                asm volatile("cp.async.cg.shared.global [%0], [%1], 16;\n" :: "r"(dst), "l"(src));
            }
        }
        asm volatile("cp.async.commit_group;\n");
        asm volatile("cp.async.wait_group 1;\n");
        __syncthreads();

        if (kt == 0) {   // extract Q fragments once (group 0 complete)
#pragma unroll
            for (int kk = 0; kk < 4; ++kk) {
                const uint32_t addr = sQ + (qRow << 7)
                    + ((((kk << 1) + qCsel) ^ (qRow & 7)) << 4);
                ldsm4(qa[kk], addr);
            }
        }

        const uint32_t Kbuf = sK + (kt & 1) * 8192;
        const uint32_t Vbuf = sV + (kt & 1) * 8192;
        const int kbase = kt * 64;

        // ---- S = Q K^T ----
        float sacc[8][4] = {};
#pragma unroll
        for (int kk = 0; kk < 4; ++kk) {
            uint32_t bk[8][2];
#pragma unroll
            for (int p = 0; p < 4; ++p) {
                const int row = p * 16 + kRowSel;
                const uint32_t addr = Kbuf + (row << 7)
                    + ((((kk << 1) + kPar) ^ lane7) << 4);
                uint32_t t[4];
                ldsm4(t, addr);
                bk[2 * p][0] = t[0]; bk[2 * p][1] = t[1];
                bk[2 * p + 1][0] = t[2]; bk[2 * p + 1][1] = t[3];
            }
#pragma unroll
            for (int nt = 0; nt < 8; ++nt)
                mma16816(sacc[nt], qa[kk], bk[nt][0], bk[nt][1]);
        }

        // ---- causal mask (diagonal tiles only) ----
        const int r0g = qbase + wrow + (lane >> 2);
        if (kbase + 63 > qbase + wrow) {
#pragma unroll
            for (int nt = 0; nt < 8; ++nt) {
                const int cg = kbase + nt * 8 + 2 * (lane & 3);
#pragma unroll
                for (int j = 0; j < 2; ++j) {
                    if (cg + j > r0g)     sacc[nt][j]     = -1e30f;
                    if (cg + j > r0g + 8) sacc[nt][2 + j] = -1e30f;
                }
            }
        }

        // ---- online softmax ----
        float mx0 = sacc[0][0], mx1 = sacc[0][2];
#pragma unroll
        for (int nt = 0; nt < 8; ++nt) {
            mx0 = fmaxf(mx0, fmaxf(sacc[nt][0], sacc[nt][1]));
            mx1 = fmaxf(mx1, fmaxf(sacc[nt][2], sacc[nt][3]));
        }
        mx0 = fmaxf(mx0, __shfl_xor_sync(0xffffffffu, mx0, 1));
        mx0 = fmaxf(mx0, __shfl_xor_sync(0xffffffffu, mx0, 2));
        mx1 = fmaxf(mx1, __shfl_xor_sync(0xffffffffu, mx1, 1));
        mx1 = fmaxf(mx1, __shfl_xor_sync(0xffffffffu, mx1, 2));

        const float mn0 = fmaxf(mrow0, mx0);
        const float mn1 = fmaxf(mrow1, mx1);
        const float alpha0 = ex2f(mrow0 - mn0);
        const float alpha1 = ex2f(mrow1 - mn1);
        mrow0 = mn0; mrow1 = mn1;

        uint32_t ph[8][2];
#pragma unroll
        for (int nt = 0; nt < 8; ++nt) {
            ph[nt][0] = h2ex2(packh2(sacc[nt][0] - mn0, sacc[nt][1] - mn0));
            ph[nt][1] = h2ex2(packh2(sacc[nt][2] - mn1, sacc[nt][3] - mn1));
        }
#pragma unroll
        for (int nt = 0; nt < 8; ++nt) {
            oacc[nt][0] *= alpha0; oacc[nt][1] *= alpha0;
            oacc[nt][2] *= alpha1; oacc[nt][3] *= alpha1;
        }
        lacc[0] *= alpha0; lacc[1] *= alpha0;
        lacc[2] *= alpha1; lacc[3] *= alpha1;

        // ---- O += P V ; l += P 1 ----
#pragma unroll
        for (int kt16 = 0; kt16 < 4; ++kt16) {
            uint32_t pa[4];
            pa[0] = ph[2 * kt16][0];
            pa[1] = ph[2 * kt16][1];
            pa[2] = ph[2 * kt16 + 1][0];
            pa[3] = ph[2 * kt16 + 1][1];

            uint32_t bv[8][2];
#pragma unroll
            for (int p = 0; p < 4; ++p) {
                const int row = kt16 * 16 + vRow;
                const uint32_t addr = Vbuf + (row << 7)
                    + ((((p << 1) + vCsel) ^ (row & 7)) << 4);
                uint32_t t[4];
                ldsm4t(t, addr);
                bv[2 * p][0] = t[0]; bv[2 * p][1] = t[1];
                bv[2 * p + 1][0] = t[2]; bv[2 * p + 1][1] = t[3];
            }
#pragma unroll
            for (int nt = 0; nt < 8; ++nt)
                mma16816(oacc[nt], pa, bv[nt][0], bv[nt][1]);
            mma16816(lacc, pa, 0x3C003C00u, 0x3C003C00u);
        }
    }

    // ---- normalize + write z (half) ----
    const float inv0 = 1.f / lacc[0];
    const float inv1 = 1.f / lacc[2];
    __half* const Zg = g_zh + base;
    const int r0 = qbase + wrow + (lane >> 2);
#pragma unroll
    for (int nt = 0; nt < 8; ++nt) {
        const int c = nt * 8 + 2 * (lane & 3);
        *(__half2*)(Zg + (size_t)r0 * 1024 + c) =
            __floats2half2_rn(oacc[nt][0] * inv0, oacc[nt][1] * inv0);
        *(__half2*)(Zg + (size_t)(r0 + 8) * 1024 + c) =
            __floats2half2_rn(oacc[nt][2] * inv1, oacc[nt][3] * inv1);
    }
}

// ---------------------------------------------------------------------------
extern "C" void kernel_launch(void* const* d_in, const int* in_sizes, int n_in,
                              void* d_out, int out_size)
{
    (void)in_sizes; (void)n_in; (void)out_size;
    const float* x  = (const float*)d_in[0];
    const float* Wq = (const float*)d_in[1];
    const float* Wk = (const float*)d_in[2];
    const float* Wv = (const float*)d_in[3];
    const float* Wo = (const float*)d_in[4];
    const float* bq = (const float*)d_in[5];
    const float* bk = (const float*)d_in[6];
    const float* bv = (const float*)d_in[7];
    const float* bo = (const float*)d_in[8];
    float* out = (float*)d_out;

    cudaFuncSetAttribute(flash_kernel,
                         cudaFuncAttributeMaxDynamicSharedMemorySize, FL_SMEM);
    cudaFuncSetAttribute(qkv_kernel,
                         cudaFuncAttributeMaxDynamicSharedMemorySize, TG_SMEM);
    cudaFuncSetAttribute(out_kernel,
                         cudaFuncAttributeMaxDynamicSharedMemorySize, TG_SMEM);

    __half *p_xh, *p_wh;
    cudaGetSymbolAddress((void**)&p_xh, g_xh);
    cudaGetSymbolAddress((void**)&p_wh, g_wh);

    pack_half_kernel<<<4096, 256>>>(x,  p_xh);
    pack_half_kernel<<<1024, 256>>>(Wq, p_wh + 0 * 1048576);
    pack_half_kernel<<<1024, 256>>>(Wk, p_wh + 1 * 1048576);
    pack_half_kernel<<<1024, 256>>>(Wv, p_wh + 2 * 1048576);
    transpose_wo_kernel<<<4096, 256>>>(Wo);

    qkv_kernel<<<dim3(8, 32, 3), 256, TG_SMEM>>>(bq, bk, bv);
    flash_kernel<<<dim3(16, 16, 2), 256, FL_SMEM>>>();
    out_kernel<<<dim3(8, 32, 1), 256, TG_SMEM>>>(bo, out);
}

// round 5
// speedup vs baseline: 7.7677x; 1.1124x over previous
#include <cuda_runtime.h>
#include <cuda_fp16.h>
#include <cstdint>

// Problem constants
#define B_   2
#define S_   2048
#define D_   1024
#define H_   16
#define DH_  64
#define M_   4096      /* B_*S_ rows */

// Q scale: 1/sqrt(64) * log2(e)  (log2e folded so softmax uses pure 2^x)
#define QSCALE 0.1803368801111204f

// Scratch (static device globals — no runtime allocation)
__device__ __half g_xh  [M_ * D_];
__device__ __half g_wh  [3 * D_ * D_];
__device__ __half g_woth[D_ * D_];
__device__ __half g_qh  [M_ * D_];
__device__ __half g_kh  [M_ * D_];
__device__ __half g_vh  [M_ * D_];
__device__ __half g_zh  [M_ * D_];

// ---------------------------------------------------------------------------
// small helpers
// ---------------------------------------------------------------------------
__device__ __forceinline__ float ex2f(float x)
{
    float y;
    asm("ex2.approx.f32 %0, %1;" : "=f"(y) : "f"(x));
    return y;
}
__device__ __forceinline__ uint32_t packh2(float lo, float hi)
{
    uint32_t d;
    asm("cvt.rn.f16x2.f32 %0, %1, %2;" : "=r"(d) : "f"(hi), "f"(lo));
    return d;
}
__device__ __forceinline__ uint32_t h2ex2(uint32_t x)
{
    uint32_t d;
    asm("ex2.approx.f16x2 %0, %1;" : "=r"(d) : "r"(x));
    return d;
}
__device__ __forceinline__ void mma16816(float c[4], const uint32_t a[4],
                                         uint32_t b0, uint32_t b1)
{
    asm volatile(
        "mma.sync.aligned.m16n8k16.row.col.f32.f16.f16.f32 "
        "{%0,%1,%2,%3},{%4,%5,%6,%7},{%8,%9},{%0,%1,%2,%3};"
        : "+f"(c[0]), "+f"(c[1]), "+f"(c[2]), "+f"(c[3])
        : "r"(a[0]), "r"(a[1]), "r"(a[2]), "r"(a[3]), "r"(b0), "r"(b1));
}
__device__ __forceinline__ void ldsm4(uint32_t r[4], uint32_t addr)
{
    asm volatile("ldmatrix.sync.aligned.m8n8.x4.shared.b16 {%0,%1,%2,%3}, [%4];"
                 : "=r"(r[0]), "=r"(r[1]), "=r"(r[2]), "=r"(r[3]) : "r"(addr));
}
__device__ __forceinline__ void ldsm4t(uint32_t r[4], uint32_t addr)
{
    asm volatile("ldmatrix.sync.aligned.m8n8.x4.trans.shared.b16 {%0,%1,%2,%3}, [%4];"
                 : "=r"(r[0]), "=r"(r[1]), "=r"(r[2]), "=r"(r[3]) : "r"(addr));
}

// ---------------------------------------------------------------------------
// Fused prep: pack x -> half, pack W_QKV -> half, transpose+pack W_O.
// Grid: [0,4096) x | [4096,7168) W_QKV | [7168,11264) W_O
// ---------------------------------------------------------------------------
__global__ void __launch_bounds__(256)
prep_kernel(const float* __restrict__ x,
            const float* __restrict__ wq, const float* __restrict__ wk,
            const float* __restrict__ wv, const float* __restrict__ wo)
{
    const int blk = blockIdx.x;
    if (blk < 4096) {
        const int i = blk * 256 + threadIdx.x;
        const float4 v = ((const float4*)x)[i];
        ((__half2*)g_xh)[2 * i]     = __floats2half2_rn(v.x, v.y);
        ((__half2*)g_xh)[2 * i + 1] = __floats2half2_rn(v.z, v.w);
    } else if (blk < 7168) {
        const int z   = (blk - 4096) >> 10;
        const int b10 = (blk - 4096) & 1023;
        const float* src = (z == 0) ? wq : (z == 1) ? wk : wv;
        __half* dst = g_wh + (size_t)z * 1048576;
        const int i = b10 * 256 + threadIdx.x;
        const float4 v = ((const float4*)src)[i];
        ((__half2*)dst)[2 * i]     = __floats2half2_rn(v.x, v.y);
        ((__half2*)dst)[2 * i + 1] = __floats2half2_rn(v.z, v.w);
    } else {
        const int idx = (blk - 7168) * 256 + threadIdx.x;   // 0 .. 1048575
        const int h = idx & 63;
        const int i = (idx >> 6) & 15;
        const int d = idx >> 10;
        g_woth[idx] = __float2half(wo[((size_t)i * 1024 + d) * 64 + h]);
    }
}

// ---------------------------------------------------------------------------
// FP16 tensor GEMM: C[4096,1024] = A[4096,1024] * W[1024,1024]^T + bias
// Block tile 256x128, BK=64, 8 warps (4 row-groups x 2 col-groups),
// warp tile 64x64, mma m16n8k16, cp.async double buffer, SW128 swizzle.
// ---------------------------------------------------------------------------
#define HG_SMEM (1024 + 2 * 49152)   /* bias + 2 x (A 32KB + B 16KB) */

__device__ __forceinline__ void hstage(const __half* __restrict__ A,
                                       const __half* __restrict__ W,
                                       int rowBase, int colBase, int kt,
                                       uint32_t sdst, int tid)
{
#pragma unroll
    for (int i = 0; i < 12; ++i) {
        const int cid = tid + i * 256;          // 0..3071
        const int isA = (cid < 2048);
        const int row = isA ? (cid >> 3) : ((cid - 2048) >> 3);
        const int kc  = cid & 7;
        const __half* src = (isA
            ? A + (size_t)(rowBase + row) * 1024
            : W + (size_t)(colBase + row) * 1024) + kt * 64 + kc * 8;
        const uint32_t dst = sdst + (isA ? 0 : 32768)
                           + (row << 7) + ((kc ^ (row & 7)) << 4);
        asm volatile("cp.async.cg.shared.global [%0], [%1], 16;\n" :: "r"(dst), "l"(src));
    }
}

template <int OUT_HALF>
__device__ __forceinline__ void hgemm256(const __half* __restrict__ A,
                                         const __half* __restrict__ W,
                                         const float* __restrict__ bias,
                                         void* __restrict__ Cout,
                                         float oscale, char* sm)
{
    float* const biasSm = (float*)sm;
    const uint32_t sBuf = (uint32_t)__cvta_generic_to_shared(sm) + 1024;

    const int tid  = threadIdx.x;
    const int lane = tid & 31;
    const int w    = tid >> 5;
    const int wr   = w & 3;       // 4 x 64-row groups
    const int wc   = w >> 2;      // 2 x 64-col groups
    const int rowBase = blockIdx.y * 256;
    const int colBase = blockIdx.x * 128;

    float acc[4][8][4] = {};

    const int lane7 = lane & 7;
    const int rA    = wr * 64 + (lane & 15);
    const int cA    = lane >> 4;
    const int rB    = wc * 64 + ((lane >> 4) << 3) + lane7;  // + p*16
    const int bPar  = (lane >> 3) & 1;

    if (tid < 128) biasSm[tid] = bias[colBase + tid];

    hstage(A, W, rowBase, colBase, 0, sBuf, tid);
    asm volatile("cp.async.commit_group;\n");

    for (int kt = 0; kt < 16; ++kt) {
        __syncthreads();
        if (kt + 1 < 16)
            hstage(A, W, rowBase, colBase, kt + 1, sBuf + ((kt + 1) & 1) * 49152, tid);
        asm volatile("cp.async.commit_group;\n");
        asm volatile("cp.async.wait_group 1;\n");
        __syncthreads();

        const uint32_t aBase = sBuf + (kt & 1) * 49152;
        const uint32_t bBase = aBase + 32768;
#pragma unroll
        for (int kk = 0; kk < 4; ++kk) {
            uint32_t a[4][4], b[8][2];
#pragma unroll
            for (int mt = 0; mt < 4; ++mt) {
                const int row = rA + mt * 16;
                const uint32_t addr = aBase + (row << 7)
                    + ((((kk << 1) + cA) ^ (row & 7)) << 4);
                ldsm4(a[mt], addr);
            }
#pragma unroll
            for (int p = 0; p < 4; ++p) {
                const int row = rB + p * 16;
                const uint32_t addr = bBase + (row << 7)
                    + ((((kk << 1) + bPar) ^ lane7) << 4);
                uint32_t t[4];
                ldsm4(t, addr);
                b[2 * p][0] = t[0]; b[2 * p][1] = t[1];
                b[2 * p + 1][0] = t[2]; b[2 * p + 1][1] = t[3];
            }
#pragma unroll
            for (int mt = 0; mt < 4; ++mt)
#pragma unroll
                for (int nt = 0; nt < 8; ++nt)
                    mma16816(acc[mt][nt], a[mt], b[nt][0], b[nt][1]);
        }
    }

    // Epilogue
#pragma unroll
    for (int mt = 0; mt < 4; ++mt) {
        const int r0 = rowBase + wr * 64 + mt * 16 + (lane >> 2);
#pragma unroll
        for (int half_ = 0; half_ < 2; ++half_) {
            const int r = r0 + half_ * 8;
#pragma unroll
            for (int nt = 0; nt < 8; ++nt) {
                const int cl = wc * 64 + nt * 8 + 2 * (lane & 3);
                const int c  = colBase + cl;
                const float v0 = (acc[mt][nt][half_ * 2 + 0] + biasSm[cl])     * oscale;
                const float v1 = (acc[mt][nt][half_ * 2 + 1] + biasSm[cl + 1]) * oscale;
                if (OUT_HALF) {
                    *(__half2*)((__half*)Cout + (size_t)r * 1024 + c) =
                        __floats2half2_rn(v0, v1);
                } else {
                    *(float2*)((float*)Cout + (size_t)r * 1024 + c) =
                        make_float2(v0, v1);
                }
            }
        }
    }
}

// QKV projection: blockIdx.z selects Q/K/V (q scaled by QSCALE)
__global__ void __launch_bounds__(256, 1)
qkv_kernel(const float* __restrict__ bq, const float* __restrict__ bk,
           const float* __restrict__ bv)
{
    extern __shared__ char smc[];
    const int z = blockIdx.z;
    const __half* W = g_wh + (size_t)z * 1048576;
    const float* b  = (z == 0) ? bq : (z == 1) ? bk : bv;
    __half* O       = (z == 0) ? g_qh : (z == 1) ? g_kh : g_vh;
    const float sc  = (z == 0) ? QSCALE : 1.f;
    hgemm256<1>(g_xh, W, b, O, sc, smc);
}

// Output projection: out = z @ WoT^T + b_O (float out)
__global__ void __launch_bounds__(256, 1)
out_kernel(const float* __restrict__ bo, float* __restrict__ out)
{
    extern __shared__ char smc[];
    hgemm256<0>(g_zh, g_woth, bo, out, 1.f, smc);
}

// ---------------------------------------------------------------------------
// FP16 tensor-core flash attention, BKEY=128.
// CTA: 128 q-rows, 8 warps x 16 rows, key tiles of 128, DH=64.
// Q fragments register-resident; K/V double-buffered cp.async smem.
// Softmax exps via ex2.approx.f16x2; row-sum via ones-column mma.
// ---------------------------------------------------------------------------
#define FL_SMEM (16384 + 32768 + 32768)   /* Q + K(2x16K) + V(2x16K) = 80KB */

__global__ void __launch_bounds__(256, 1)
flash_kernel()
{
    extern __shared__ __align__(16) char smc[];
    const uint32_t sQ = (uint32_t)__cvta_generic_to_shared(smc);
    const uint32_t sK = sQ + 16384;
    const uint32_t sV = sK + 32768;

    const int qt  = 15 - blockIdx.x;  // heavy CTAs first
    const int h   = blockIdx.y;
    const int bb  = blockIdx.z;
    const int tid = threadIdx.x;
    const int lane = tid & 31;
    const int wid  = tid >> 5;
    const int lane7 = lane & 7;

    const int qbase = qt * 128;
    const int wrow  = wid * 16;
    const size_t base = (size_t)bb * S_ * 1024 + (size_t)h * 64;
    const __half* const Qg = g_qh + base;
    const __half* const Kg = g_kh + base;
    const __half* const Vg = g_vh + base;

    // ---- stage Q (128 rows) ----
#pragma unroll
    for (int i = 0; i < 4; ++i) {
        const int cid = tid + i * 256;          // 0..1023
        const int row = cid >> 3;
        const int kc  = cid & 7;
        const __half* src = Qg + (size_t)(qbase + row) * 1024 + kc * 8;
        const uint32_t dst = sQ + (row << 7) + ((kc ^ (row & 7)) << 4);
        asm volatile("cp.async.cg.shared.global [%0], [%1], 16;\n" :: "r"(dst), "l"(src));
    }
    // ---- stage K/V tile 0 (128 keys) ----
#pragma unroll
    for (int i = 0; i < 8; ++i) {
        const int cid = tid + i * 256;          // 0..2047 : 1024 K, 1024 V
        const int row = (cid >> 3) & 127;
        const int kc  = cid & 7;
        const __half* src = ((cid < 1024) ? Kg : Vg) + (size_t)row * 1024 + kc * 8;
        const uint32_t dst = ((cid < 1024) ? sK : sV)
                           + (row << 7) + ((kc ^ (row & 7)) << 4);
        asm volatile("cp.async.cg.shared.global [%0], [%1], 16;\n" :: "r"(dst), "l"(src));
    }
    asm volatile("cp.async.commit_group;\n");

    // per-thread ldmatrix selectors
    const int qRow    = wrow + (lane & 15);
    const int qCsel   = lane >> 4;
    const int kRowSel = ((lane >> 4) << 3) + lane7;   // + p*16
    const int kPar    = (lane >> 3) & 1;
    const int vRow    = lane & 15;                    // + kt16*16
    const int vCsel   = lane >> 4;                    // + 2*p

    uint32_t qa[4][4];
    float oacc[8][4] = {};
    float lacc[4] = {};
    float mrow0 = -1e30f, mrow1 = -1e30f;

    const int ntile = qt + 1;
    for (int kt = 0; kt < ntile; ++kt) {
        __syncthreads();  // buffer-reuse guard
        if (kt + 1 < ntile) {
            const int kb2 = (kt + 1) * 128;
            const uint32_t boff = ((kt + 1) & 1) * 16384;
#pragma unroll
            for (int i = 0; i < 8; ++i) {
                const int cid = tid + i * 256;
                const int row = (cid >> 3) & 127;
                const int kc  = cid & 7;
                const __half* src = ((cid < 1024) ? Kg : Vg)
                                  + (size_t)(kb2 + row) * 1024 + kc * 8;
                const uint32_t dst = ((cid < 1024) ? sK : sV) + boff
                                   + (row << 7) + ((kc ^ (row & 7)) << 4);
                asm volatile("cp.async.cg.shared.global [%0], [%1], 16;\n" :: "r"(dst), "l"(src));
            }
        }
        asm volatile("cp.async.commit_group;\n");
        asm volatile("cp.async.wait_group 1;\n");
        __syncthreads();

        if (kt == 0) {   // extract Q fragments once (group 0 complete)
#pragma unroll
            for (int kk = 0; kk < 4; ++kk) {
                const uint32_t addr = sQ + (qRow << 7)
                    + ((((kk << 1) + qCsel) ^ (qRow & 7)) << 4);
                ldsm4(qa[kk], addr);
            }
        }

        const uint32_t Kbuf = sK + (kt & 1) * 16384;
        const uint32_t Vbuf = sV + (kt & 1) * 16384;
        const int kbase = kt * 128;

        // ---- S = Q K^T  (16 n-tiles of 8 keys) ----
        float sacc[16][4] = {};
#pragma unroll
        for (int kk = 0; kk < 4; ++kk) {
            uint32_t bk[16][2];
#pragma unroll
            for (int p = 0; p < 8; ++p) {
                const int row = p * 16 + kRowSel;
                const uint32_t addr = Kbuf + (row << 7)
                    + ((((kk << 1) + kPar) ^ lane7) << 4);
                uint32_t t[4];
                ldsm4(t, addr);
                bk[2 * p][0] = t[0]; bk[2 * p][1] = t[1];
                bk[2 * p + 1][0] = t[2]; bk[2 * p + 1][1] = t[3];
            }
#pragma unroll
            for (int nt = 0; nt < 16; ++nt)
                mma16816(sacc[nt], qa[kk], bk[nt][0], bk[nt][1]);
        }

        // ---- causal mask (diagonal tile only: kt == qt) ----
        if (kt == qt) {
            const int r0g = qbase + wrow + (lane >> 2);
#pragma unroll
            for (int nt = 0; nt < 16; ++nt) {
                const int cg = kbase + nt * 8 + 2 * (lane & 3);
#pragma unroll
                for (int j = 0; j < 2; ++j) {
                    if (cg + j > r0g)     sacc[nt][j]     = -1e30f;
                    if (cg + j > r0g + 8) sacc[nt][2 + j] = -1e30f;
                }
            }
        }

        // ---- online softmax ----
        float mx0 = sacc[0][0], mx1 = sacc[0][2];
#pragma unroll
        for (int nt = 0; nt < 16; ++nt) {
            mx0 = fmaxf(mx0, fmaxf(sacc[nt][0], sacc[nt][1]));
            mx1 = fmaxf(mx1, fmaxf(sacc[nt][2], sacc[nt][3]));
        }
        mx0 = fmaxf(mx0, __shfl_xor_sync(0xffffffffu, mx0, 1));
        mx0 = fmaxf(mx0, __shfl_xor_sync(0xffffffffu, mx0, 2));
        mx1 = fmaxf(mx1, __shfl_xor_sync(0xffffffffu, mx1, 1));
        mx1 = fmaxf(mx1, __shfl_xor_sync(0xffffffffu, mx1, 2));

        const float mn0 = fmaxf(mrow0, mx0);
        const float mn1 = fmaxf(mrow1, mx1);
        const float alpha0 = ex2f(mrow0 - mn0);
        const float alpha1 = ex2f(mrow1 - mn1);
        mrow0 = mn0; mrow1 = mn1;

        uint32_t ph[16][2];
#pragma unroll
        for (int nt = 0; nt < 16; ++nt) {
            ph[nt][0] = h2ex2(packh2(sacc[nt][0] - mn0, sacc[nt][1] - mn0));
            ph[nt][1] = h2ex2(packh2(sacc[nt][2] - mn1, sacc[nt][3] - mn1));
        }
#pragma unroll
        for (int nt = 0; nt < 8; ++nt) {
            oacc[nt][0] *= alpha0; oacc[nt][1] *= alpha0;
            oacc[nt][2] *= alpha1; oacc[nt][3] *= alpha1;
        }
        lacc[0] *= alpha0; lacc[1] *= alpha0;
        lacc[2] *= alpha1; lacc[3] *= alpha1;

        // ---- O += P V ; l += P 1 ----
#pragma unroll
        for (int kt16 = 0; kt16 < 8; ++kt16) {
            uint32_t pa[4];
            pa[0] = ph[2 * kt16][0];
            pa[1] = ph[2 * kt16][1];
            pa[2] = ph[2 * kt16 + 1][0];
            pa[3] = ph[2 * kt16 + 1][1];

            uint32_t bv[8][2];
#pragma unroll
            for (int p = 0; p < 4; ++p) {
                const int row = kt16 * 16 + vRow;
                const uint32_t addr = Vbuf + (row << 7)
                    + ((((p << 1) + vCsel) ^ (row & 7)) << 4);
                uint32_t t[4];
                ldsm4t(t, addr);
                bv[2 * p][0] = t[0]; bv[2 * p][1] = t[1];
                bv[2 * p + 1][0] = t[2]; bv[2 * p + 1][1] = t[3];
            }
#pragma unroll
            for (int nt = 0; nt < 8; ++nt)
                mma16816(oacc[nt], pa, bv[nt][0], bv[nt][1]);
            mma16816(lacc, pa, 0x3C003C00u, 0x3C003C00u);
        }
    }

    // ---- normalize + write z (half) ----
    const float inv0 = 1.f / lacc[0];
    const float inv1 = 1.f / lacc[2];
    __half* const Zg = g_zh + base;
    const int r0 = qbase + wrow + (lane >> 2);
#pragma unroll
    for (int nt = 0; nt < 8; ++nt) {
        const int c = nt * 8 + 2 * (lane & 3);
        *(__half2*)(Zg + (size_t)r0 * 1024 + c) =
            __floats2half2_rn(oacc[nt][0] * inv0, oacc[nt][1] * inv0);
        *(__half2*)(Zg + (size_t)(r0 + 8) * 1024 + c) =
            __floats2half2_rn(oacc[nt][2] * inv1, oacc[nt][3] * inv1);
    }
}

// ---------------------------------------------------------------------------
extern "C" void kernel_launch(void* const* d_in, const int* in_sizes, int n_in,
                              void* d_out, int out_size)
{
    (void)in_sizes; (void)n_in; (void)out_size;
    const float* x  = (const float*)d_in[0];
    const float* Wq = (const float*)d_in[1];
    const float* Wk = (const float*)d_in[2];
    const float* Wv = (const float*)d_in[3];
    const float* Wo = (const float*)d_in[4];
    const float* bq = (const float*)d_in[5];
    const float* bk = (const float*)d_in[6];
    const float* bv = (const float*)d_in[7];
    const float* bo = (const float*)d_in[8];
    float* out = (float*)d_out;

    cudaFuncSetAttribute(flash_kernel,
                         cudaFuncAttributeMaxDynamicSharedMemorySize, FL_SMEM);
    cudaFuncSetAttribute(qkv_kernel,
                         cudaFuncAttributeMaxDynamicSharedMemorySize, HG_SMEM);
    cudaFuncSetAttribute(out_kernel,
                         cudaFuncAttributeMaxDynamicSharedMemorySize, HG_SMEM);

    prep_kernel<<<11264, 256>>>(x, Wq, Wk, Wv, Wo);
    qkv_kernel<<<dim3(8, 16, 3), 256, HG_SMEM>>>(bq, bk, bv);
    flash_kernel<<<dim3(16, 16, 2), 256, FL_SMEM>>>();
    out_kernel<<<dim3(8, 16, 1), 256, HG_SMEM>>>(bo, out);
}